// round 15
// baseline (speedup 1.0000x reference)
#include <cuda_runtime.h>
#include <cuda_fp16.h>
#include <cstdint>
#include <cstddef>

#define NN   50000
#define EE   800000
#define INC  512
#define OUTC 256
#define DECD 256
#define NBLK 391        // ceil(NN/128)
#define SBLK 196        // ceil(NN/256)

// Scratch (device globals — no allocation allowed)
__device__ float  g_dinv[NN];
__device__ int    g_flag[NN];     // zero at entry (BSS init + k_unflag at exit)
__device__ int    g_cnt[NN];      // zero at entry (BSS init + k_scan3 clears)
__device__ int    g_rowptr[NN + 1];
__device__ int    g_bsum[256];
__device__ int    g_cur[NN];
__device__ int    g_esrc[EE];
__device__ __half g_bufA[(size_t)NN * OUTC];
__device__ __half g_bufB[(size_t)NN * OUTC];
__device__ __half g_bufC[(size_t)NN * OUTC];

// ---------------------------------------------------------------- CSR build
__global__ void k_deg(const int* __restrict__ dst) {
    int e = blockIdx.x * blockDim.x + threadIdx.x;
    if (e < EE) atomicAdd(&g_cnt[dst[e]], 1);
}
__global__ void k_scan1() {
    __shared__ int s[256];
    int gid = blockIdx.x * 256 + threadIdx.x;
    int v = (gid < NN) ? g_cnt[gid] : 0;
    s[threadIdx.x] = v;
    __syncthreads();
#pragma unroll
    for (int off = 1; off < 256; off <<= 1) {
        int t = (threadIdx.x >= off) ? s[threadIdx.x - off] : 0;
        __syncthreads();
        s[threadIdx.x] += t;
        __syncthreads();
    }
    if (gid < NN) g_rowptr[gid] = s[threadIdx.x] - v;
    if (threadIdx.x == 255) g_bsum[blockIdx.x] = s[255];
}
__global__ void k_scan2() {
    __shared__ int s[256];
    int v = (threadIdx.x < SBLK) ? g_bsum[threadIdx.x] : 0;
    s[threadIdx.x] = v;
    __syncthreads();
#pragma unroll
    for (int off = 1; off < 256; off <<= 1) {
        int t = (threadIdx.x >= off) ? s[threadIdx.x - off] : 0;
        __syncthreads();
        s[threadIdx.x] += t;
        __syncthreads();
    }
    if (threadIdx.x < SBLK) g_bsum[threadIdx.x] = s[threadIdx.x] - v;
    if (threadIdx.x == 0) g_rowptr[NN] = EE;
}
__global__ void k_scan3() {     // global rowptr + cur + dinv; self-clean cnt
    int gid = blockIdx.x * 256 + threadIdx.x;
    if (gid < NN) {
        int r = g_rowptr[gid] + g_bsum[blockIdx.x];
        g_rowptr[gid] = r;
        g_cur[gid] = r;
        g_dinv[gid] = rsqrtf((float)g_cnt[gid] + 1.0f);
        g_cnt[gid] = 0;                       // ready for next run
    }
}
__global__ void k_fill(const int* __restrict__ src, const int* __restrict__ dst) {
    int e = blockIdx.x * blockDim.x + threadIdx.x;
    if (e < EE) {
        int p = atomicAdd(&g_cur[dst[e]], 1);
        g_esrc[p] = src[e];
    }
}
__global__ void k_flag(const int* __restrict__ midx, int nm) {
    int i = blockIdx.x * blockDim.x + threadIdx.x;
    if (i < nm) g_flag[midx[i]] = 1;
}
__global__ void k_unflag(const int* __restrict__ midx, int nm) {
    int i = blockIdx.x * blockDim.x + threadIdx.x;
    if (i < nm) g_flag[midx[i]] = 0;
}

// ---------------------------------------------------------------- output tail (x copy + midx convert)
__global__ void k_tail(const float* __restrict__ x, const int* __restrict__ midx,
                       float* __restrict__ out, int nm) {
    const int NX = NN * (INC / 4);
    int i = blockIdx.x * 256 + threadIdx.x;
    if (i < NX)
        *(float4*)(out + (size_t)NN * INC + (size_t)i * 4) = ((const float4*)x)[i];
    int j = i - NX;
    if (j >= 0 && j < nm)
        out[2 * (size_t)NN * INC + j] = (float)midx[j];
}

// ---------------------------------------------------------------- pull-mode aggregation (half in/out, fp32 accum)
__global__ void __launch_bounds__(256)
k_gather(const __half* __restrict__ h, const float* __restrict__ bias,
         __half* __restrict__ z) {
    const int node = blockIdx.x * 4 + (threadIdx.x >> 6);
    const int lane = threadIdx.x & 63;
    if (node >= NN) return;
    const int beg = g_rowptr[node];
    const int end = g_rowptr[node + 1];
    const float dn = g_dinv[node];

    const float4 bz = *(const float4*)(bias + lane * 4);
    uint2 hv = *(const uint2*)(h + (size_t)node * OUTC + lane * 4);
    float2 h0 = __half22float2(*(const __half2*)&hv.x);
    float2 h1 = __half22float2(*(const __half2*)&hv.y);
    const float s = dn * dn;
    float4 acc;
    acc.x = h0.x * s + bz.x;  acc.y = h0.y * s + bz.y;
    acc.z = h1.x * s + bz.z;  acc.w = h1.y * s + bz.w;

    int sidx = (beg < end) ? __ldg(&g_esrc[beg]) : 0;
    for (int i = beg; i < end; i++) {
        int nsidx = (i + 1 < end) ? __ldg(&g_esrc[i + 1]) : 0;
        float c = g_dinv[sidx] * dn;
        uint2 v = *(const uint2*)(h + (size_t)sidx * OUTC + lane * 4);
        float2 v0 = __half22float2(*(const __half2*)&v.x);
        float2 v1 = __half22float2(*(const __half2*)&v.y);
        acc.x += v0.x * c;  acc.y += v0.y * c;
        acc.z += v1.x * c;  acc.w += v1.y * c;
        sidx = nsidx;
    }
    uint2 st;
    *(__half2*)&st.x = __floats2half2_rn(acc.x, acc.y);
    *(__half2*)&st.y = __floats2half2_rn(acc.z, acc.w);
    *(uint2*)(z + (size_t)node * OUTC + lane * 4) = st;
}

// ---------------------------------------------------------------- fp16 mma.sync GEMM (ldmatrix, wide-N 128x256 tile, 512 thr)
__device__ __forceinline__ void mma16(float* c, const uint32_t* a, const uint32_t* b) {
    asm volatile(
        "mma.sync.aligned.m16n8k16.row.col.f32.f16.f16.f32 "
        "{%0,%1,%2,%3}, {%4,%5,%6,%7}, {%8,%9}, {%0,%1,%2,%3};"
        : "+f"(c[0]), "+f"(c[1]), "+f"(c[2]), "+f"(c[3])
        : "r"(a[0]), "r"(a[1]), "r"(a[2]), "r"(a[3]), "r"(b[0]), "r"(b[1]));
}
__device__ __forceinline__ void ldsm_x4(uint32_t* r, uint32_t sa) {
    asm volatile("ldmatrix.sync.aligned.m8n8.x4.shared.b16 {%0,%1,%2,%3}, [%4];"
                 : "=r"(r[0]), "=r"(r[1]), "=r"(r[2]), "=r"(r[3]) : "r"(sa));
}
__device__ __forceinline__ void ldsm_x4t(uint32_t* r, uint32_t sa) {
    asm volatile("ldmatrix.sync.aligned.m8n8.x4.trans.shared.b16 {%0,%1,%2,%3}, [%4];"
                 : "=r"(r[0]), "=r"(r[1]), "=r"(r[2]), "=r"(r[3]) : "r"(sa));
}
__device__ __forceinline__ uint2 pack4h(const float4& v) {
    __half2 h0 = __floats2half2_rn(v.x, v.y);
    __half2 h1 = __floats2half2_rn(v.z, v.w);
    uint2 r;
    r.x = *(const uint32_t*)&h0;
    r.y = *(const uint32_t*)&h1;
    return r;
}

// C[128-row tile, 256-col tile] = op(A[M,K_TOT]) @ W[K_TOT,N_TOT]
// 512 threads: 16 warps = 2(M) x 8(N); warp tile 64x32; acc 64 regs/thread.
template<int N_TOT, int K_TOT, bool INF32, bool MASK, bool RELU, bool OUTF32>
__global__ void __launch_bounds__(512)
k_mma(const void* __restrict__ Ain, const float* __restrict__ W,
      void* __restrict__ outp, const float* __restrict__ bias,
      const float* __restrict__ mtok)
{
    constexpr int NC   = K_TOT / 32;
    constexpr int ASTR = 40;               // halves per A smem row (32 + 8 pad)
    constexpr int BSTR = 264;              // halves per B smem row (256 + 8 pad)
    constexpr int ASZ  = 128 * ASTR;
    constexpr int BSZ  = 32 * BSTR;

    extern __shared__ __half sm[];
    __half* Abuf = sm;                     // 2 * ASZ
    __half* Bbuf = sm + 2 * ASZ;           // 2 * BSZ

    const int tid   = threadIdx.x;
    const int wid   = tid >> 5;
    const int lane  = tid & 31;
    const int g     = lane >> 2;
    const int tig   = lane & 3;
    const int warpM = wid >> 3;            // 0..1 -> 64 rows
    const int warpN = wid & 7;             // 0..7 -> 32 cols
    const int m0    = blockIdx.y * 128;
    const int n0    = blockIdx.x * 256;

    float acc[4][4][4];
#pragma unroll
    for (int mt = 0; mt < 4; mt++)
#pragma unroll
        for (int nt = 0; nt < 4; nt++)
#pragma unroll
            for (int i = 0; i < 4; i++) acc[mt][nt][i] = 0.0f;

    uint2 rA[2], rB[4];

    auto ldg = [&](int c) {
        const int k0 = c * 32;
#pragma unroll
        for (int t = 0; t < 2; t++) {      // A: 1024 quad tasks / 512 thr
            int idx = tid + t * 512;
            int r = idx >> 3, q = idx & 7;
            int gr = m0 + r;
            if (INF32) {
                const float* A = (const float*)Ain;
                float4 v = make_float4(0.f, 0.f, 0.f, 0.f);
                if (gr < NN) {
                    const float* p;
                    if (MASK && g_flag[gr]) p = mtok + k0 + q * 4;
                    else                    p = A + (size_t)gr * K_TOT + k0 + q * 4;
                    v = *(const float4*)p;
                }
                rA[t] = pack4h(v);
            } else {
                const __half* A = (const __half*)Ain;
                uint2 v = make_uint2(0u, 0u);
                if (gr < NN)
                    v = *(const uint2*)(A + (size_t)gr * K_TOT + k0 + q * 4);
                if (RELU) {
                    const __half2 z2 = __float2half2_rn(0.f);
                    *(__half2*)&v.x = __hmax2(*(__half2*)&v.x, z2);
                    *(__half2*)&v.y = __hmax2(*(__half2*)&v.y, z2);
                }
                rA[t] = v;
            }
        }
#pragma unroll
        for (int t = 0; t < 4; t++) {      // B: 32 x 64 float4 tasks / 512 thr
            int idx = tid + t * 512;
            int kk = idx >> 6, n4 = idx & 63;
            float4 v = *(const float4*)(W + (size_t)(k0 + kk) * N_TOT + n0 + n4 * 4);
            rB[t] = pack4h(v);
        }
    };
    auto sts = [&](int b) {
        __half* As = Abuf + b * ASZ;
        __half* Bs = Bbuf + b * BSZ;
#pragma unroll
        for (int t = 0; t < 2; t++) {
            int idx = tid + t * 512;
            int r = idx >> 3, q = idx & 7;
            *(uint2*)(As + r * ASTR + q * 4) = rA[t];
        }
#pragma unroll
        for (int t = 0; t < 4; t++) {
            int idx = tid + t * 512;
            int kk = idx >> 6, n4 = idx & 63;
            *(uint2*)(Bs + kk * BSTR + n4 * 4) = rB[t];
        }
    };

    const uint32_t aRow = (uint32_t)(warpM * 64 + (lane & 15));
    const uint32_t aOff = (aRow * ASTR + (uint32_t)((lane >> 4) * 8)) * 2;
    const uint32_t bKr  = (uint32_t)(((lane >> 3) & 1) * 8 + (lane & 7));
    const uint32_t bNc  = (uint32_t)(warpN * 32 + (lane >> 4) * 8);

    ldg(0);
    sts(0);
    __syncthreads();

    for (int c = 0; c < NC; c++) {
        const int b = c & 1;
        if (c + 1 < NC) ldg(c + 1);        // global loads in flight during mma

        const uint32_t Asb = (uint32_t)__cvta_generic_to_shared(Abuf + b * ASZ);
        const uint32_t Bsb = (uint32_t)__cvta_generic_to_shared(Bbuf + b * BSZ);
#pragma unroll
        for (int kt = 0; kt < 2; kt++) {
            uint32_t af[4][4], bf[4][2];
#pragma unroll
            for (int mt = 0; mt < 4; mt++)
                ldsm_x4(af[mt], Asb + aOff + (uint32_t)((mt * 16 * ASTR + kt * 16) * 2));
#pragma unroll
            for (int p = 0; p < 2; p++) {
                uint32_t r[4];
                ldsm_x4t(r, Bsb + (uint32_t)((((kt * 16 + bKr) * BSTR) + bNc + p * 16) * 2));
                bf[2 * p][0] = r[0];  bf[2 * p][1] = r[1];
                bf[2 * p + 1][0] = r[2];  bf[2 * p + 1][1] = r[3];
            }
#pragma unroll
            for (int mt = 0; mt < 4; mt++)
#pragma unroll
                for (int nt = 0; nt < 4; nt++)
                    mma16(acc[mt][nt], af[mt], bf[nt]);
        }
        // single barrier per chunk: write NEXT chunk into the buffer not read
        // this iteration (its last readers passed the previous barrier).
        if (c + 1 < NC) sts((c + 1) & 1);
        __syncthreads();
    }

    // epilogue
#pragma unroll
    for (int mt = 0; mt < 4; mt++) {
        const int row0 = m0 + warpM * 64 + mt * 16 + g;
        const int row1 = row0 + 8;
#pragma unroll
        for (int nt = 0; nt < 4; nt++) {
            const int col = n0 + warpN * 32 + nt * 8 + 2 * tig;
            const float* cc = acc[mt][nt];
            if (OUTF32) {
                float* outF = (float*)outp;
                const float2 bz = *(const float2*)(bias + col);
                if (row0 < NN)
                    *(float2*)(outF + (size_t)row0 * N_TOT + col) =
                        make_float2(cc[0] + bz.x, cc[1] + bz.y);
                if (row1 < NN)
                    *(float2*)(outF + (size_t)row1 * N_TOT + col) =
                        make_float2(cc[2] + bz.x, cc[3] + bz.y);
            } else {
                __half* outH = (__half*)outp;
                if (row0 < NN) {
                    __half2 h = __floats2half2_rn(cc[0], cc[1]);
                    *(uint32_t*)(outH + (size_t)row0 * N_TOT + col) = *(const uint32_t*)&h;
                }
                if (row1 < NN) {
                    __half2 h = __floats2half2_rn(cc[2], cc[3]);
                    *(uint32_t*)(outH + (size_t)row1 * N_TOT + col) = *(const uint32_t*)&h;
                }
            }
        }
    }
}

// ---------------------------------------------------------------- launch
extern "C" void kernel_launch(void* const* d_in, const int* in_sizes, int n_in,
                              void* d_out, int out_size) {
    const float* x    = (const float*)d_in[0];
    const int*   eidx = (const int*)d_in[1];
    const int*   midx = (const int*)d_in[2];
    const float* mtok = (const float*)d_in[3];
    const float* encW = (const float*)d_in[4];
    const float* encb = (const float*)d_in[5];
    const float* decW = (const float*)d_in[6];
    const float* decb = (const float*)d_in[7];
    const float* mlpW = (const float*)d_in[8];
    const float* mlpb = (const float*)d_in[9];

    const int nm = in_sizes[2];
    const int* src = eidx;
    const int* dst = eidx + EE;

    __half *bufA, *bufB, *bufC;
    cudaGetSymbolAddress((void**)&bufA, g_bufA);
    cudaGetSymbolAddress((void**)&bufB, g_bufB);
    cudaGetSymbolAddress((void**)&bufC, g_bufC);
    float* out = (float*)d_out;

    const int SMEM = (2 * 128 * 40 + 2 * 32 * 264) * 2;   // 54272 B
    static bool attrDone = false;
    if (!attrDone) {
        cudaFuncSetAttribute(k_mma<OUTC, INC,  true,  true,  false, false>,
                             cudaFuncAttributeMaxDynamicSharedMemorySize, SMEM);
        cudaFuncSetAttribute(k_mma<OUTC, OUTC, false, false, false, false>,
                             cudaFuncAttributeMaxDynamicSharedMemorySize, SMEM);
        cudaFuncSetAttribute(k_mma<INC,  DECD, false, false, true,  true>,
                             cudaFuncAttributeMaxDynamicSharedMemorySize, SMEM);
        attrDone = true;
    }

    // side streams + events (host objects, created once)
    static cudaStream_t sCsr = nullptr, sTail = nullptr;
    static cudaEvent_t  eFork = nullptr, eCsr = nullptr, eTail = nullptr;
    if (!sCsr) {
        cudaStreamCreateWithFlags(&sCsr, cudaStreamNonBlocking);
        cudaStreamCreateWithFlags(&sTail, cudaStreamNonBlocking);
        cudaEventCreateWithFlags(&eFork, cudaEventDisableTiming);
        cudaEventCreateWithFlags(&eCsr, cudaEventDisableTiming);
        cudaEventCreateWithFlags(&eTail, cudaEventDisableTiming);
    }

    // fork side streams from the capture stream
    cudaEventRecord(eFork, 0);
    cudaStreamWaitEvent(sCsr, eFork, 0);
    cudaStreamWaitEvent(sTail, eFork, 0);

    // --- sCsr: CSR build + dinv (needed only by gather1); cnt pre-zeroed ---
    k_deg<<<(EE + 255) / 256, 256, 0, sCsr>>>(dst);
    k_scan1<<<SBLK, 256, 0, sCsr>>>();
    k_scan2<<<1, 256, 0, sCsr>>>();
    k_scan3<<<SBLK, 256, 0, sCsr>>>();
    k_fill<<<(EE + 255) / 256, 256, 0, sCsr>>>(src, dst);
    cudaEventRecord(eCsr, sCsr);

    // --- sTail: output slots 1+2 (independent of everything) ---
    k_tail<<<(NN * (INC / 4) + nm + 255) / 256, 256, 0, sTail>>>(x, midx, out, nm);
    cudaEventRecord(eTail, sTail);

    // --- main stream: flags (pre-zeroed) -> GEMM1 (overlaps CSR build) ---
    k_flag<<<(nm + 255) / 256, 256>>>(midx, nm);
    k_mma<OUTC, INC, true, true, false, false><<<dim3(1, NBLK), 512, SMEM>>>(
        x, encW, bufA, nullptr, mtok);

    cudaStreamWaitEvent(0, eCsr, 0);      // join CSR before gather1

    const int gatherBlocks = (NN + 3) / 4;
    k_gather<<<gatherBlocks, 256>>>(bufA, encb, bufB);

    k_mma<OUTC, OUTC, false, false, false, false><<<dim3(1, NBLK), 512, SMEM>>>(
        bufB, decW, bufA, nullptr, nullptr);
    k_gather<<<gatherBlocks, 256>>>(bufA, decb, bufC);

    k_mma<INC, DECD, false, false, true, true><<<dim3(2, NBLK), 512, SMEM>>>(
        bufC, mlpW, out, mlpb, nullptr);

    // restore clean flag state for next run (off the result path)
    k_unflag<<<(nm + 255) / 256, 256>>>(midx, nm);

    cudaStreamWaitEvent(0, eTail, 0);     // join tail copy before returning
}

// round 17
// speedup vs baseline: 1.0856x; 1.0856x over previous
#include <cuda_runtime.h>
#include <cuda_fp16.h>
#include <cstdint>
#include <cstddef>

#define NN   50000
#define EE   800000
#define INC  512
#define OUTC 256
#define DECD 256
#define NBLK 391        // ceil(NN/128)
#define SBLK 196        // ceil(NN/256)

// Scratch (device globals — no allocation allowed)
__device__ float  g_dinv[NN];
__device__ int    g_flag[NN];     // zero at entry (BSS init + k_unflag at exit)
__device__ int    g_cnt[NN];      // zero at entry (BSS init + k_scan3 clears)
__device__ int    g_rowptr[NN + 1];
__device__ int    g_bsum[256];
__device__ int    g_cur[NN];
__device__ int    g_esrc[EE];
__device__ __half g_bufA[(size_t)NN * OUTC];
__device__ __half g_bufB[(size_t)NN * OUTC];
__device__ __half g_bufC[(size_t)NN * OUTC];

// ---------------------------------------------------------------- CSR build
__global__ void k_deg(const int* __restrict__ dst) {
    int e = blockIdx.x * blockDim.x + threadIdx.x;
    if (e < EE) atomicAdd(&g_cnt[dst[e]], 1);
}
__global__ void k_scan1() {
    __shared__ int s[256];
    int gid = blockIdx.x * 256 + threadIdx.x;
    int v = (gid < NN) ? g_cnt[gid] : 0;
    s[threadIdx.x] = v;
    __syncthreads();
#pragma unroll
    for (int off = 1; off < 256; off <<= 1) {
        int t = (threadIdx.x >= off) ? s[threadIdx.x - off] : 0;
        __syncthreads();
        s[threadIdx.x] += t;
        __syncthreads();
    }
    if (gid < NN) g_rowptr[gid] = s[threadIdx.x] - v;
    if (threadIdx.x == 255) g_bsum[blockIdx.x] = s[255];
}
__global__ void k_scan2() {
    __shared__ int s[256];
    int v = (threadIdx.x < SBLK) ? g_bsum[threadIdx.x] : 0;
    s[threadIdx.x] = v;
    __syncthreads();
#pragma unroll
    for (int off = 1; off < 256; off <<= 1) {
        int t = (threadIdx.x >= off) ? s[threadIdx.x - off] : 0;
        __syncthreads();
        s[threadIdx.x] += t;
        __syncthreads();
    }
    if (threadIdx.x < SBLK) g_bsum[threadIdx.x] = s[threadIdx.x] - v;
    if (threadIdx.x == 0) g_rowptr[NN] = EE;
}
__global__ void k_scan3() {     // global rowptr + cur + dinv; self-clean cnt
    int gid = blockIdx.x * 256 + threadIdx.x;
    if (gid < NN) {
        int r = g_rowptr[gid] + g_bsum[blockIdx.x];
        g_rowptr[gid] = r;
        g_cur[gid] = r;
        g_dinv[gid] = rsqrtf((float)g_cnt[gid] + 1.0f);
        g_cnt[gid] = 0;                       // ready for next run
    }
}
__global__ void k_fill(const int* __restrict__ src, const int* __restrict__ dst) {
    int e = blockIdx.x * blockDim.x + threadIdx.x;
    if (e < EE) {
        int p = atomicAdd(&g_cur[dst[e]], 1);
        g_esrc[p] = src[e];
    }
}
__global__ void k_flag(const int* __restrict__ midx, int nm) {
    int i = blockIdx.x * blockDim.x + threadIdx.x;
    if (i < nm) g_flag[midx[i]] = 1;
}
__global__ void k_unflag(const int* __restrict__ midx, int nm) {
    int i = blockIdx.x * blockDim.x + threadIdx.x;
    if (i < nm) g_flag[midx[i]] = 0;
}

// ---------------------------------------------------------------- output tail (x copy + midx convert)
__global__ void k_tail(const float* __restrict__ x, const int* __restrict__ midx,
                       float* __restrict__ out, int nm) {
    const int NX = NN * (INC / 4);
    int i = blockIdx.x * 256 + threadIdx.x;
    if (i < NX)
        *(float4*)(out + (size_t)NN * INC + (size_t)i * 4) = ((const float4*)x)[i];
    int j = i - NX;
    if (j >= 0 && j < nm)
        out[2 * (size_t)NN * INC + j] = (float)midx[j];
}

// ---------------------------------------------------------------- pull-mode aggregation (half in/out, fp32 accum)
__global__ void __launch_bounds__(256)
k_gather(const __half* __restrict__ h, const float* __restrict__ bias,
         __half* __restrict__ z) {
    const int node = blockIdx.x * 4 + (threadIdx.x >> 6);
    const int lane = threadIdx.x & 63;
    if (node >= NN) return;
    const int beg = g_rowptr[node];
    const int end = g_rowptr[node + 1];
    const float dn = g_dinv[node];

    const float4 bz = *(const float4*)(bias + lane * 4);
    uint2 hv = *(const uint2*)(h + (size_t)node * OUTC + lane * 4);
    float2 h0 = __half22float2(*(const __half2*)&hv.x);
    float2 h1 = __half22float2(*(const __half2*)&hv.y);
    const float s = dn * dn;
    float4 acc;
    acc.x = h0.x * s + bz.x;  acc.y = h0.y * s + bz.y;
    acc.z = h1.x * s + bz.z;  acc.w = h1.y * s + bz.w;

    int i = beg;
    for (; i + 1 < end; i += 2) {          // 2 row-gathers in flight
        int s0 = __ldg(&g_esrc[i]);
        int s1 = __ldg(&g_esrc[i + 1]);
        float c0 = g_dinv[s0] * dn;
        float c1 = g_dinv[s1] * dn;
        uint2 u0 = *(const uint2*)(h + (size_t)s0 * OUTC + lane * 4);
        uint2 u1 = *(const uint2*)(h + (size_t)s1 * OUTC + lane * 4);
        float2 a0 = __half22float2(*(const __half2*)&u0.x);
        float2 a1 = __half22float2(*(const __half2*)&u0.y);
        float2 b0 = __half22float2(*(const __half2*)&u1.x);
        float2 b1 = __half22float2(*(const __half2*)&u1.y);
        acc.x += a0.x * c0 + b0.x * c1;
        acc.y += a0.y * c0 + b0.y * c1;
        acc.z += a1.x * c0 + b1.x * c1;
        acc.w += a1.y * c0 + b1.y * c1;
    }
    if (i < end) {
        int s0 = __ldg(&g_esrc[i]);
        float c0 = g_dinv[s0] * dn;
        uint2 u0 = *(const uint2*)(h + (size_t)s0 * OUTC + lane * 4);
        float2 a0 = __half22float2(*(const __half2*)&u0.x);
        float2 a1 = __half22float2(*(const __half2*)&u0.y);
        acc.x += a0.x * c0;  acc.y += a0.y * c0;
        acc.z += a1.x * c0;  acc.w += a1.y * c0;
    }
    uint2 st;
    *(__half2*)&st.x = __floats2half2_rn(acc.x, acc.y);
    *(__half2*)&st.y = __floats2half2_rn(acc.z, acc.w);
    *(uint2*)(z + (size_t)node * OUTC + lane * 4) = st;
}

// ---------------------------------------------------------------- fp16 mma.sync GEMM (ldmatrix, 128x128 tile, 256 thr)
__device__ __forceinline__ void mma16(float* c, const uint32_t* a, const uint32_t* b) {
    asm volatile(
        "mma.sync.aligned.m16n8k16.row.col.f32.f16.f16.f32 "
        "{%0,%1,%2,%3}, {%4,%5,%6,%7}, {%8,%9}, {%0,%1,%2,%3};"
        : "+f"(c[0]), "+f"(c[1]), "+f"(c[2]), "+f"(c[3])
        : "r"(a[0]), "r"(a[1]), "r"(a[2]), "r"(a[3]), "r"(b[0]), "r"(b[1]));
}
__device__ __forceinline__ void ldsm_x4(uint32_t* r, uint32_t sa) {
    asm volatile("ldmatrix.sync.aligned.m8n8.x4.shared.b16 {%0,%1,%2,%3}, [%4];"
                 : "=r"(r[0]), "=r"(r[1]), "=r"(r[2]), "=r"(r[3]) : "r"(sa));
}
__device__ __forceinline__ void ldsm_x4t(uint32_t* r, uint32_t sa) {
    asm volatile("ldmatrix.sync.aligned.m8n8.x4.trans.shared.b16 {%0,%1,%2,%3}, [%4];"
                 : "=r"(r[0]), "=r"(r[1]), "=r"(r[2]), "=r"(r[3]) : "r"(sa));
}
__device__ __forceinline__ uint2 pack4h(const float4& v) {
    __half2 h0 = __floats2half2_rn(v.x, v.y);
    __half2 h1 = __floats2half2_rn(v.z, v.w);
    uint2 r;
    r.x = *(const uint32_t*)&h0;
    r.y = *(const uint32_t*)&h1;
    return r;
}

template<int N_TOT, int K_TOT, bool INF32, bool MASK, bool RELU, bool OUTF32>
__global__ void __launch_bounds__(256)
k_mma(const void* __restrict__ Ain, const float* __restrict__ W,
      void* __restrict__ outp, const float* __restrict__ bias,
      const float* __restrict__ mtok)
{
    constexpr int NC   = K_TOT / 32;
    constexpr int ASTR = 40;
    constexpr int BSTR = 136;
    constexpr int ASZ  = 128 * ASTR;
    constexpr int BSZ  = 32 * BSTR;

    extern __shared__ __half sm[];
    __half* Abuf = sm;
    __half* Bbuf = sm + 2 * ASZ;

    const int tid   = threadIdx.x;
    const int wid   = tid >> 5;
    const int lane  = tid & 31;
    const int g     = lane >> 2;
    const int tig   = lane & 3;
    const int warpM = wid >> 2;
    const int warpN = wid & 3;
    const int m0    = blockIdx.y * 128;
    const int n0    = blockIdx.x * 128;

    float acc[4][4][4];
#pragma unroll
    for (int mt = 0; mt < 4; mt++)
#pragma unroll
        for (int nt = 0; nt < 4; nt++)
#pragma unroll
            for (int i = 0; i < 4; i++) acc[mt][nt][i] = 0.0f;

    uint2 rA[4], rB[4];

    auto ldg = [&](int c) {
        const int k0 = c * 32;
#pragma unroll
        for (int t = 0; t < 4; t++) {
            int idx = tid + t * 256;
            int r = idx >> 3, q = idx & 7;
            int gr = m0 + r;
            if (INF32) {
                const float* A = (const float*)Ain;
                float4 v = make_float4(0.f, 0.f, 0.f, 0.f);
                if (gr < NN) {
                    const float* p;
                    if (MASK && g_flag[gr]) p = mtok + k0 + q * 4;
                    else                    p = A + (size_t)gr * K_TOT + k0 + q * 4;
                    v = *(const float4*)p;
                }
                rA[t] = pack4h(v);
            } else {
                const __half* A = (const __half*)Ain;
                uint2 v = make_uint2(0u, 0u);
                if (gr < NN)
                    v = *(const uint2*)(A + (size_t)gr * K_TOT + k0 + q * 4);
                if (RELU) {
                    const __half2 z2 = __float2half2_rn(0.f);
                    *(__half2*)&v.x = __hmax2(*(__half2*)&v.x, z2);
                    *(__half2*)&v.y = __hmax2(*(__half2*)&v.y, z2);
                }
                rA[t] = v;
            }
        }
#pragma unroll
        for (int t = 0; t < 4; t++) {
            int idx = tid + t * 256;
            int kk = idx >> 5, n4 = idx & 31;
            float4 v = *(const float4*)(W + (size_t)(k0 + kk) * N_TOT + n0 + n4 * 4);
            rB[t] = pack4h(v);
        }
    };
    auto sts = [&](int b) {
        __half* As = Abuf + b * ASZ;
        __half* Bs = Bbuf + b * BSZ;
#pragma unroll
        for (int t = 0; t < 4; t++) {
            int idx = tid + t * 256;
            int r = idx >> 3, q = idx & 7;
            *(uint2*)(As + r * ASTR + q * 4) = rA[t];
        }
#pragma unroll
        for (int t = 0; t < 4; t++) {
            int idx = tid + t * 256;
            int kk = idx >> 5, n4 = idx & 31;
            *(uint2*)(Bs + kk * BSTR + n4 * 4) = rB[t];
        }
    };

    const uint32_t aRow = (uint32_t)(warpM * 64 + (lane & 15));
    const uint32_t aOff = (aRow * ASTR + (uint32_t)((lane >> 4) * 8)) * 2;
    const uint32_t bKr  = (uint32_t)(((lane >> 3) & 1) * 8 + (lane & 7));
    const uint32_t bNc  = (uint32_t)(warpN * 32 + (lane >> 4) * 8);

    ldg(0);
    sts(0);
    __syncthreads();

    for (int c = 0; c < NC; c++) {
        const int b = c & 1;
        if (c + 1 < NC) ldg(c + 1);        // global loads in flight during mma

        const uint32_t Asb = (uint32_t)__cvta_generic_to_shared(Abuf + b * ASZ);
        const uint32_t Bsb = (uint32_t)__cvta_generic_to_shared(Bbuf + b * BSZ);
#pragma unroll
        for (int kt = 0; kt < 2; kt++) {
            uint32_t af[4][4], bf[4][2];
#pragma unroll
            for (int mt = 0; mt < 4; mt++)
                ldsm_x4(af[mt], Asb + aOff + (uint32_t)((mt * 16 * ASTR + kt * 16) * 2));
#pragma unroll
            for (int p = 0; p < 2; p++) {
                uint32_t r[4];
                ldsm_x4t(r, Bsb + (uint32_t)((((kt * 16 + bKr) * BSTR) + bNc + p * 16) * 2));
                bf[2 * p][0] = r[0];  bf[2 * p][1] = r[1];
                bf[2 * p + 1][0] = r[2];  bf[2 * p + 1][1] = r[3];
            }
#pragma unroll
            for (int mt = 0; mt < 4; mt++)
#pragma unroll
                for (int nt = 0; nt < 4; nt++)
                    mma16(acc[mt][nt], af[mt], bf[nt]);
        }
        // single barrier per chunk: write NEXT chunk into the buffer not read
        // this iteration (its last readers passed the previous barrier).
        if (c + 1 < NC) sts((c + 1) & 1);
        __syncthreads();
    }

    // epilogue
#pragma unroll
    for (int mt = 0; mt < 4; mt++) {
        const int row0 = m0 + warpM * 64 + mt * 16 + g;
        const int row1 = row0 + 8;
#pragma unroll
        for (int nt = 0; nt < 4; nt++) {
            const int col = n0 + warpN * 32 + nt * 8 + 2 * tig;
            const float* cc = acc[mt][nt];
            if (OUTF32) {
                float* outF = (float*)outp;
                const float2 bz = *(const float2*)(bias + col);
                if (row0 < NN)
                    *(float2*)(outF + (size_t)row0 * N_TOT + col) =
                        make_float2(cc[0] + bz.x, cc[1] + bz.y);
                if (row1 < NN)
                    *(float2*)(outF + (size_t)row1 * N_TOT + col) =
                        make_float2(cc[2] + bz.x, cc[3] + bz.y);
            } else {
                __half* outH = (__half*)outp;
                if (row0 < NN) {
                    __half2 h = __floats2half2_rn(cc[0], cc[1]);
                    *(uint32_t*)(outH + (size_t)row0 * N_TOT + col) = *(const uint32_t*)&h;
                }
                if (row1 < NN) {
                    __half2 h = __floats2half2_rn(cc[2], cc[3]);
                    *(uint32_t*)(outH + (size_t)row1 * N_TOT + col) = *(const uint32_t*)&h;
                }
            }
        }
    }
}

// ---------------------------------------------------------------- launch
extern "C" void kernel_launch(void* const* d_in, const int* in_sizes, int n_in,
                              void* d_out, int out_size) {
    const float* x    = (const float*)d_in[0];
    const int*   eidx = (const int*)d_in[1];
    const int*   midx = (const int*)d_in[2];
    const float* mtok = (const float*)d_in[3];
    const float* encW = (const float*)d_in[4];
    const float* encb = (const float*)d_in[5];
    const float* decW = (const float*)d_in[6];
    const float* decb = (const float*)d_in[7];
    const float* mlpW = (const float*)d_in[8];
    const float* mlpb = (const float*)d_in[9];

    const int nm = in_sizes[2];
    const int* src = eidx;
    const int* dst = eidx + EE;

    __half *bufA, *bufB, *bufC;
    cudaGetSymbolAddress((void**)&bufA, g_bufA);
    cudaGetSymbolAddress((void**)&bufB, g_bufB);
    cudaGetSymbolAddress((void**)&bufC, g_bufC);
    float* out = (float*)d_out;

    const int SMEM = (2 * 128 * 40 + 2 * 32 * 136) * 2;   // 37888 B

    // side streams + events (host objects, created once)
    static cudaStream_t sCsr = nullptr, sTail = nullptr;
    static cudaEvent_t  eFork = nullptr, eCsr = nullptr, eTail = nullptr;
    if (!sCsr) {
        cudaStreamCreateWithFlags(&sCsr, cudaStreamNonBlocking);
        cudaStreamCreateWithFlags(&sTail, cudaStreamNonBlocking);
        cudaEventCreateWithFlags(&eFork, cudaEventDisableTiming);
        cudaEventCreateWithFlags(&eCsr, cudaEventDisableTiming);
        cudaEventCreateWithFlags(&eTail, cudaEventDisableTiming);
    }

    // fork side streams from the capture stream
    cudaEventRecord(eFork, 0);
    cudaStreamWaitEvent(sCsr, eFork, 0);
    cudaStreamWaitEvent(sTail, eFork, 0);

    // --- sCsr: CSR build + dinv (needed only by gather1); cnt pre-zeroed ---
    k_deg<<<(EE + 255) / 256, 256, 0, sCsr>>>(dst);
    k_scan1<<<SBLK, 256, 0, sCsr>>>();
    k_scan2<<<1, 256, 0, sCsr>>>();
    k_scan3<<<SBLK, 256, 0, sCsr>>>();
    k_fill<<<(EE + 255) / 256, 256, 0, sCsr>>>(src, dst);
    cudaEventRecord(eCsr, sCsr);

    // --- sTail: output slots 1+2 (independent of everything) ---
    k_tail<<<(NN * (INC / 4) + nm + 255) / 256, 256, 0, sTail>>>(x, midx, out, nm);
    cudaEventRecord(eTail, sTail);

    // --- main stream: flags (pre-zeroed) -> GEMM1 (overlaps CSR build) ---
    k_flag<<<(nm + 255) / 256, 256>>>(midx, nm);
    k_mma<OUTC, INC, true, true, false, false><<<dim3(OUTC / 128, NBLK), 256, SMEM>>>(
        x, encW, bufA, nullptr, mtok);

    cudaStreamWaitEvent(0, eCsr, 0);      // join CSR before gather1

    const int gatherBlocks = (NN + 3) / 4;
    k_gather<<<gatherBlocks, 256>>>(bufA, encb, bufB);

    k_mma<OUTC, OUTC, false, false, false, false><<<dim3(OUTC / 128, NBLK), 256, SMEM>>>(
        bufB, decW, bufA, nullptr, nullptr);
    k_gather<<<gatherBlocks, 256>>>(bufA, decb, bufC);

    k_mma<INC, DECD, false, false, true, true><<<dim3(INC / 128, NBLK), 256, SMEM>>>(
        bufC, mlpW, out, mlpb, nullptr);

    // restore clean flag state for next run (off the result path)
    k_unflag<<<(nm + 255) / 256, 256>>>(midx, nm);

    cudaStreamWaitEvent(0, eTail, 0);     // join tail copy before returning
}